// round 4
// baseline (speedup 1.0000x reference)
#include <cuda_runtime.h>
#include <cstdint>

// ----------------------------------------------------------------------------
// ResBlock_71021579207010 — GB300 (sm_103a)
//
// Reference collapses: ste_sign(relu(.)) == +1, so conv1/bn1 are dead and
// conv2 output is a per-channel constant (two variants: t<16 pad region vs
// t>=16). Remaining data-dependent work is the k=1 binarized shortcut GEMM:
//   out[b,t,f] = relu( c[f, t<16] + sum_c sign(x[b,t,c]) * sign(w_sc[c,f]) )
// Binary dot via ballot-packed bits + xor/popc: dot = 128 - 2*popc(px^pw).
//
// Shapes: B=32, T=8192, C=F=128, rows = B*T = 262144.
// R3 postmortem: 1-block prologue is bound by single-SM mem service (~10us gap
// incl. launches). R4: split prologue across 36 blocks (partials, no atomics
// so graph replay stays deterministic) + tiny reduce kernel. Main: cap regs
// via launch_bounds(256,6) + unroll 4 to lift occupancy 52% -> ~70%.
// ----------------------------------------------------------------------------

__device__ int g_partial[32][128];                  // per-block sign counts of w2
__device__ __align__(16) unsigned g_pw[128][4];     // packed sign bits of w_sc per f
__device__ __align__(16) float    g_add_ge[128];    // relu(bn2(S0+S1)) + 128
__device__ __align__(16) float    g_add_lt[128];    // relu(bn2(S1))    + 128

// P1: 36 blocks x 128 threads. Blocks 0..31: block s counts signs over 8
// consecutive (k,c)-rows m = s*8+i of w2 (flattened [2,128,128]); s<16 -> k=0,
// s>=16 -> k=1. Blocks 32..35: block 32+j packs w_sc sign word j for every f.
__global__ void __launch_bounds__(128) prologue1(const float* __restrict__ w2,
                                                 const float* __restrict__ w_sc)
{
    const int f = threadIdx.x;  // 0..127
    const int b = blockIdx.x;
    if (b < 32) {
        const int m0 = b * 8;
        int cnt = 0;
        #pragma unroll
        for (int i = 0; i < 8; ++i)
            cnt += (w2[(m0 + i) * 128 + f] >= 0.f) ? 1 : 0;
        g_partial[b][f] = cnt;
    } else {
        // word j, bit l <-> channel c = 4*l + j ; w_sc is [1,128,128]: idx c*128+f
        const int j = b - 32;
        unsigned p = 0u;
        #pragma unroll
        for (int l = 0; l < 32; ++l)
            if (w_sc[(4 * l + j) * 128 + f] >= 0.f) p |= (1u << l);
        g_pw[f][j] = p;
    }
}

// P2: 1 block x 128 threads. Reduce the 32 partials (all L2-hit, coalesced
// across f) and fold bn2 into the two per-channel additive constants.
__global__ void __launch_bounds__(128) prologue2(const float* __restrict__ beta2,
                                                 const float* __restrict__ mean2,
                                                 const float* __restrict__ var2)
{
    const int f = threadIdx.x;
    int t0 = 0, t1 = 0;
    #pragma unroll
    for (int s = 0; s < 16; ++s)  t0 += g_partial[s][f];
    #pragma unroll
    for (int s = 16; s < 32; ++s) t1 += g_partial[s][f];
    const float S0 = 2.f * (float)t0 - 128.f;   // sum of signs, k=0
    const float S1 = 2.f * (float)t1 - 128.f;   // k=1
    const float inv = rsqrtf(var2[f] + 1e-3f);
    const float cge = fmaxf(fmaf(S0 + S1 - mean2[f], inv, beta2[f]), 0.f);
    const float clt = fmaxf(fmaf(S1      - mean2[f], inv, beta2[f]), 0.f);
    g_add_ge[f] = cge + 128.f;   // fold the "+128" of dot = 128 - 2*pc
    g_add_lt[f] = clt + 128.f;
}

// Row-loop body shared by both paths. HAS_LT selects per-row pad handling.
template <bool HAS_LT>
__device__ __forceinline__ void do_rows(const float* __restrict__ x,
                                        float* __restrict__ out,
                                        size_t row0, int lane,
                                        const uint4& pw0, const uint4& pw1,
                                        const uint4& pw2, const uint4& pw3,
                                        const float4& age, const float4& alt)
{
    #pragma unroll 4
    for (int r = 0; r < 16; ++r) {
        const size_t row = row0 + r;

        // 128 floats of this row: lane reads channels [4*lane, 4*lane+3].
        const float4 v = reinterpret_cast<const float4*>(x + row * 128)[lane];

        // Pack row sign bits: word j, bit l = sign(x[4l + j])  (>=0 -> 1).
        const unsigned px0 = __ballot_sync(0xffffffffu, v.x >= 0.f);
        const unsigned px1 = __ballot_sync(0xffffffffu, v.y >= 0.f);
        const unsigned px2 = __ballot_sync(0xffffffffu, v.z >= 0.f);
        const unsigned px3 = __ballot_sync(0xffffffffu, v.w >= 0.f);

        float a0, a1, a2, a3;
        if (HAS_LT) {
            const bool lt = ((row & 8191u) < 16u);  // conv2 causal pad region
            a0 = lt ? alt.x : age.x;
            a1 = lt ? alt.y : age.y;
            a2 = lt ? alt.z : age.z;
            a3 = lt ? alt.w : age.w;
        } else {
            a0 = age.x; a1 = age.y; a2 = age.z; a3 = age.w;
        }

        const int pc0 = __popc(px0 ^ pw0.x) + __popc(px1 ^ pw0.y)
                      + __popc(px2 ^ pw0.z) + __popc(px3 ^ pw0.w);
        const int pc1 = __popc(px0 ^ pw1.x) + __popc(px1 ^ pw1.y)
                      + __popc(px2 ^ pw1.z) + __popc(px3 ^ pw1.w);
        const int pc2 = __popc(px0 ^ pw2.x) + __popc(px1 ^ pw2.y)
                      + __popc(px2 ^ pw2.z) + __popc(px3 ^ pw2.w);
        const int pc3 = __popc(px0 ^ pw3.x) + __popc(px1 ^ pw3.y)
                      + __popc(px2 ^ pw3.z) + __popc(px3 ^ pw3.w);

        float4 o;
        o.x = fmaxf(fmaf(-2.f, (float)pc0, a0), 0.f);
        o.y = fmaxf(fmaf(-2.f, (float)pc1, a1), 0.f);
        o.z = fmaxf(fmaf(-2.f, (float)pc2, a2), 0.f);
        o.w = fmaxf(fmaf(-2.f, (float)pc3, a3), 0.f);

        reinterpret_cast<float4*>(out + row * 128)[lane] = o;
    }
}

// Main kernel: 2048 blocks x 256 threads, 6 blocks/SM target (regs <= 42).
// Each warp owns 16 rows; each lane owns 4 consecutive f outputs (float4
// load/store). Weights/consts hoisted into registers before the row loop.
__global__ void __launch_bounds__(256, 6) resblock_main(const float* __restrict__ x,
                                                        float* __restrict__ out)
{
    const int lane = threadIdx.x & 31;
    const int warp = threadIdx.x >> 5;
    const int f0   = 4 * lane;

    // Per-lane weight columns (row-invariant): 16 u32 + 8 floats in registers.
    const uint4 pw0 = *reinterpret_cast<const uint4*>(g_pw[f0 + 0]);
    const uint4 pw1 = *reinterpret_cast<const uint4*>(g_pw[f0 + 1]);
    const uint4 pw2 = *reinterpret_cast<const uint4*>(g_pw[f0 + 2]);
    const uint4 pw3 = *reinterpret_cast<const uint4*>(g_pw[f0 + 3]);
    const float4 age = *reinterpret_cast<const float4*>(&g_add_ge[f0]);
    const float4 alt = *reinterpret_cast<const float4*>(&g_add_lt[f0]);

    const size_t row0 = (size_t)blockIdx.x * 128 + (size_t)warp * 16;

    // Rows with t<16 exist only in warp 0 of every 64th block (8192/128 = 64).
    if (warp == 0 && (blockIdx.x & 63) == 0) {
        do_rows<true >(x, out, row0, lane, pw0, pw1, pw2, pw3, age, alt);
    } else {
        do_rows<false>(x, out, row0, lane, pw0, pw1, pw2, pw3, age, alt);
    }
}

extern "C" void kernel_launch(void* const* d_in, const int* in_sizes, int n_in,
                              void* d_out, int out_size)
{
    // metadata order: x, w1, w2, w_sc, beta1, mean1, var1, beta2, mean2, var2
    const float* x     = (const float*)d_in[0];
    const float* w2    = (const float*)d_in[2];
    const float* w_sc  = (const float*)d_in[3];
    const float* beta2 = (const float*)d_in[7];
    const float* mean2 = (const float*)d_in[8];
    const float* var2  = (const float*)d_in[9];
    float* out = (float*)d_out;

    prologue1<<<36, 128>>>(w2, w_sc);
    prologue2<<<1, 128>>>(beta2, mean2, var2);
    // 262144 rows / 128 rows per block = 2048 blocks
    resblock_main<<<2048, 256>>>(x, out);
}